// round 10
// baseline (speedup 1.0000x reference)
#include <cuda_runtime.h>
#include <cuda_bf16.h>

#define Cc    9
#define OUTc  16
#define NBc   16
#define Vc    20000
#define Bc    2

// padded x: 3 float4 per row (48 B)
__device__ __align__(16) float4 xpad[Bc * Vc * 3];

__global__ __launch_bounds__(256)
void pad_kernel(const float* __restrict__ x)
{
    int r = blockIdx.x * blockDim.x + threadIdx.x;   // row over B*V
    if (r >= Bc * Vc) return;
    const float* src = x + (size_t)r * Cc;
    float4* dst = xpad + (size_t)r * 3;
    dst[0] = make_float4(__ldg(&src[0]), __ldg(&src[1]), __ldg(&src[2]), __ldg(&src[3]));
    dst[1] = make_float4(__ldg(&src[4]), __ldg(&src[5]), __ldg(&src[6]), __ldg(&src[7]));
    dst[2] = make_float4(__ldg(&src[8]), 0.0f, 0.0f, 0.0f);
}

__global__ __launch_bounds__(128, 4)
void nlayer_kernel(const float* __restrict__ W,
                   const int*   __restrict__ adj,
                   float*       __restrict__ out)
{
    __shared__ float Wsh[Cc * Cc * OUTc];    // W[c][k][o], 1296 floats
    for (int i = threadIdx.x; i < Cc * Cc * OUTc; i += blockDim.x)
        Wsh[i] = W[i];

    int tid   = blockIdx.x * blockDim.x + threadIdx.x;   // 80000 total, exact
    int group = tid >> 1;          // vertex over B*V
    int p     = tid & 1;           // neighbor half AND output half

    int b = (group >= Vc) ? 1 : 0;
    int v = group - b * Vc;
    const float4* tb = xpad + (size_t)(b * Vc) * 3;

    // center row + adjacency issued before the barrier (register loads ride over it)
    float4 c0 = __ldg(&tb[(size_t)v * 3 + 0]);
    float4 c1 = __ldg(&tb[(size_t)v * 3 + 1]);
    float4 c2 = __ldg(&tb[(size_t)v * 3 + 2]);

    const int4* adj4 = reinterpret_cast<const int4*>(adj + (size_t)v * NBc);
    int4 a0 = __ldg(&adj4[2 * p + 0]);
    int4 a1 = __ldg(&adj4[2 * p + 1]);
    int av[8] = {a0.x, a0.y, a0.z, a0.w, a1.x, a1.y, a1.z, a1.w};

    __syncthreads();

    float xv[Cc] = {c0.x, c0.y, c0.z, c0.w, c1.x, c1.y, c1.z, c1.w, c2.x};

    float s[Cc][Cc];   // s[k][c], partial over this lane's 8 neighbors
    #pragma unroll
    for (int k = 0; k < Cc; k++)
        #pragma unroll
        for (int c = 0; c < Cc; c++) s[k][c] = 0.0f;

    int deg = 0;

    // 4 bursts of 2 rows: 6 float4 in flight per burst (keeps regs <= 128)
    #pragma unroll
    for (int g = 0; g < 4; g++) {
        float4 R0[2], R1[2], R2[2];
        int vld[2];
        #pragma unroll
        for (int n = 0; n < 2; n++) {
            int an = av[g * 2 + n];
            vld[n] = (an != 0);
            deg   += vld[n];
            int ridx = vld[n] ? (an - 1) : 0;
            const float4* nr = tb + (size_t)ridx * 3;
            R0[n] = __ldg(&nr[0]);
            R1[n] = __ldg(&nr[1]);
            R2[n] = __ldg(&nr[2]);
        }

        #pragma unroll
        for (int n = 0; n < 2; n++) {
            float nbv[Cc] = {R0[n].x, R0[n].y, R0[n].z, R0[n].w,
                             R1[n].x, R1[n].y, R1[n].z, R1[n].w, R2[n].x};
            float e[Cc], sum = 0.0f;
            #pragma unroll
            for (int c = 0; c < Cc; c++) {
                e[c] = __expf(xv[c] - nbv[c]);
                sum += e[c];
            }
            float rr = vld[n] ? __fdividef(1.0f, sum) : 0.0f;

            #pragma unroll
            for (int k = 0; k < Cc; k++) {
                float qk = e[k] * rr;
                #pragma unroll
                for (int c = 0; c < Cc; c++)
                    s[k][c] = fmaf(qk, nbv[c], s[k][c]);
            }
        }
    }

    // single reduction round across the lane pair; both lanes get FULL s
    deg += __shfl_xor_sync(0xffffffffu, deg, 1);
    #pragma unroll
    for (int k = 0; k < Cc; k++)
        #pragma unroll
        for (int c = 0; c < Cc; c++)
            s[k][c] += __shfl_xor_sync(0xffffffffu, s[k][c], 1);

    float invdeg = (deg > 0) ? (1.0f / (float)deg) : 0.0f;

    // lane p contracts full s into its o-half [8p, 8p+8); no post-reduction
    float acc[8];
    #pragma unroll
    for (int o = 0; o < 8; o++) acc[o] = 0.0f;

    const float* wb = Wsh + 8 * p;
    #pragma unroll
    for (int c = 0; c < Cc; c++) {
        #pragma unroll
        for (int k = 0; k < Cc; k++) {
            float sc = s[k][c];
            const float* wr = wb + (c * Cc + k) * OUTc;
            float4 w0 = *reinterpret_cast<const float4*>(wr);
            float4 w1 = *reinterpret_cast<const float4*>(wr + 4);
            acc[0] = fmaf(sc, w0.x, acc[0]);
            acc[1] = fmaf(sc, w0.y, acc[1]);
            acc[2] = fmaf(sc, w0.z, acc[2]);
            acc[3] = fmaf(sc, w0.w, acc[3]);
            acc[4] = fmaf(sc, w1.x, acc[4]);
            acc[5] = fmaf(sc, w1.y, acc[5]);
            acc[6] = fmaf(sc, w1.z, acc[6]);
            acc[7] = fmaf(sc, w1.w, acc[7]);
        }
    }

    // lane p stores outputs [8p, 8p+8): two float4, coalesced
    float* op = out + (size_t)group * OUTc + 8 * p;
    float4 o0, o1;
    o0.x = fmaxf(acc[0] * invdeg, 0.0f);
    o0.y = fmaxf(acc[1] * invdeg, 0.0f);
    o0.z = fmaxf(acc[2] * invdeg, 0.0f);
    o0.w = fmaxf(acc[3] * invdeg, 0.0f);
    o1.x = fmaxf(acc[4] * invdeg, 0.0f);
    o1.y = fmaxf(acc[5] * invdeg, 0.0f);
    o1.z = fmaxf(acc[6] * invdeg, 0.0f);
    o1.w = fmaxf(acc[7] * invdeg, 0.0f);
    *reinterpret_cast<float4*>(op)     = o0;
    *reinterpret_cast<float4*>(op + 4) = o1;
}

extern "C" void kernel_launch(void* const* d_in, const int* in_sizes, int n_in,
                              void* d_out, int out_size)
{
    const float* x   = (const float*)d_in[0];   // (2, 20000, 9)
    const float* W   = (const float*)d_in[1];   // (9, 9, 16)
    const int*   adj = (const int*)d_in[2];     // (20000, 16)
    float*       out = (float*)d_out;           // (2, 20000, 16)

    {
        const int total   = Bc * Vc;            // 40000
        const int threads = 256;
        pad_kernel<<<(total + threads - 1) / threads, threads>>>(x);
    }
    {
        const int total   = Bc * Vc * 2;        // 80000
        const int threads = 128;
        nlayer_kernel<<<total / threads, threads>>>(W, adj, out);
    }
}

// round 11
// speedup vs baseline: 1.1115x; 1.1115x over previous
#include <cuda_runtime.h>
#include <cuda_bf16.h>

#define Cc    9
#define OUTc  16
#define NBc   16
#define Vc    20000
#define Bc    2

typedef unsigned long long u64;

__device__ __forceinline__ u64 pk2(float a, float b) {
    u64 r; asm("mov.b64 %0, {%1, %2};" : "=l"(r) : "f"(a), "f"(b)); return r;
}
__device__ __forceinline__ void upk2(u64 v, float& a, float& b) {
    asm("mov.b64 {%0, %1}, %2;" : "=f"(a), "=f"(b) : "l"(v));
}
__device__ __forceinline__ u64 ffma2(u64 a, u64 b, u64 c) {
    u64 d; asm("fma.rn.f32x2 %0, %1, %2, %3;" : "=l"(d) : "l"(a), "l"(b), "l"(c)); return d;
}

// x rows: x0..7 as 2 float4 (32B, one line), x8 separately
__device__ __align__(16) float4 xpad2[Bc * Vc * 2];
__device__ float x8arr[Bc * Vc];

__global__ __launch_bounds__(256)
void pad_kernel(const float* __restrict__ x)
{
    int r = blockIdx.x * blockDim.x + threadIdx.x;   // row over B*V
    if (r >= Bc * Vc) return;
    const float* src = x + (size_t)r * Cc;
    xpad2[r * 2 + 0] = make_float4(__ldg(&src[0]), __ldg(&src[1]), __ldg(&src[2]), __ldg(&src[3]));
    xpad2[r * 2 + 1] = make_float4(__ldg(&src[4]), __ldg(&src[5]), __ldg(&src[6]), __ldg(&src[7]));
    x8arr[r] = __ldg(&src[8]);
}

__global__ __launch_bounds__(64, 6)
void nlayer_kernel(const float* __restrict__ W,
                   const int*   __restrict__ adj,
                   float*       __restrict__ out)
{
    __shared__ __align__(16) float Wsh[Cc * Cc * OUTc];  // W[c][k][o]
    for (int i = threadIdx.x; i < Cc * Cc * OUTc; i += blockDim.x)
        Wsh[i] = W[i];

    int gid   = blockIdx.x * blockDim.x + threadIdx.x;   // 80000 total, exact
    int group = gid >> 1;          // vertex over B*V
    int p     = gid & 1;           // neighbor half AND output half

    int b = (group >= Vc) ? 1 : 0;
    int v = group - b * Vc;
    const float4* tb2 = xpad2 + (size_t)(b * Vc) * 2;
    const float*  tx8 = x8arr + (size_t)(b * Vc);

    // center + adjacency issued before the barrier
    float4 c0 = __ldg(&tb2[(size_t)v * 2 + 0]);
    float4 c1 = __ldg(&tb2[(size_t)v * 2 + 1]);
    float  cx8 = __ldg(&tx8[v]);

    const int4* adj4 = reinterpret_cast<const int4*>(adj + (size_t)v * NBc);
    int4 a0 = __ldg(&adj4[2 * p + 0]);
    int4 a1 = __ldg(&adj4[2 * p + 1]);
    int av[8] = {a0.x, a0.y, a0.z, a0.w, a1.x, a1.y, a1.z, a1.w};

    __syncthreads();

    float xv[Cc] = {c0.x, c0.y, c0.z, c0.w, c1.x, c1.y, c1.z, c1.w, cx8};

    // ---- full load front: all 8 neighbor rows in flight (MLP 24) ----
    float4 N0[8], N1[8];
    float  N8[8];
    int    vld[8];
    int    deg = 0;
    #pragma unroll
    for (int n = 0; n < 8; n++) {
        int an = av[n];
        vld[n] = (an != 0);
        deg   += vld[n];
        int ridx = vld[n] ? (an - 1) : 0;
        N0[n] = __ldg(&tb2[(size_t)ridx * 2 + 0]);
        N1[n] = __ldg(&tb2[(size_t)ridx * 2 + 1]);
        N8[n] = __ldg(&tx8[ridx]);
    }

    // s[k][c]: c0..7 packed as 4 f32x2 per k, c=8 scalar
    u64   s2[Cc][4];
    float s8c[Cc];
    #pragma unroll
    for (int k = 0; k < Cc; k++) {
        s2[k][0] = 0ULL; s2[k][1] = 0ULL; s2[k][2] = 0ULL; s2[k][3] = 0ULL;
        s8c[k] = 0.0f;
    }

    #pragma unroll
    for (int n = 0; n < 8; n++) {
        float nb[Cc] = {N0[n].x, N0[n].y, N0[n].z, N0[n].w,
                        N1[n].x, N1[n].y, N1[n].z, N1[n].w, N8[n]};
        u64 nbp[4] = {pk2(nb[0], nb[1]), pk2(nb[2], nb[3]),
                      pk2(nb[4], nb[5]), pk2(nb[6], nb[7])};

        float e[Cc], sum = 0.0f;
        #pragma unroll
        for (int c = 0; c < Cc; c++) {
            e[c] = __expf(xv[c] - nb[c]);
            sum += e[c];
        }
        float rr = vld[n] ? __fdividef(1.0f, sum) : 0.0f;

        #pragma unroll
        for (int k = 0; k < Cc; k++) {
            float qk = e[k] * rr;
            u64 qq = pk2(qk, qk);
            s2[k][0] = ffma2(qq, nbp[0], s2[k][0]);
            s2[k][1] = ffma2(qq, nbp[1], s2[k][1]);
            s2[k][2] = ffma2(qq, nbp[2], s2[k][2]);
            s2[k][3] = ffma2(qq, nbp[3], s2[k][3]);
            s8c[k]   = fmaf(qk, nb[8], s8c[k]);
        }
    }

    // single reduction across the lane pair; both lanes get FULL s
    deg += __shfl_xor_sync(0xffffffffu, deg, 1);
    #pragma unroll
    for (int k = 0; k < Cc; k++) {
        #pragma unroll
        for (int j = 0; j < 4; j++) {
            u64 o = __shfl_xor_sync(0xffffffffu, s2[k][j], 1);
            float a0f, a1f, b0f, b1f;
            upk2(s2[k][j], a0f, a1f);
            upk2(o,        b0f, b1f);
            s2[k][j] = pk2(a0f + b0f, a1f + b1f);
        }
        s8c[k] += __shfl_xor_sync(0xffffffffu, s8c[k], 1);
    }

    float invdeg = (deg > 0) ? (1.0f / (float)deg) : 0.0f;

    // lane p contracts full s into its o-half [8p, 8p+8), packed accumulators
    u64 ac[4] = {0ULL, 0ULL, 0ULL, 0ULL};
    const float* wb = Wsh + 8 * p;

    #pragma unroll
    for (int j = 0; j < 4; j++) {          // c-pairs (2j, 2j+1)
        #pragma unroll
        for (int k = 0; k < Cc; k++) {
            float sc0, sc1;
            upk2(s2[k][j], sc0, sc1);
            {
                u64 ss = pk2(sc0, sc0);
                const ulonglong2* wr = reinterpret_cast<const ulonglong2*>(
                    wb + ((2 * j) * Cc + k) * OUTc);
                ulonglong2 wA = wr[0], wB = wr[1];
                ac[0] = ffma2(ss, wA.x, ac[0]);
                ac[1] = ffma2(ss, wA.y, ac[1]);
                ac[2] = ffma2(ss, wB.x, ac[2]);
                ac[3] = ffma2(ss, wB.y, ac[3]);
            }
            {
                u64 ss = pk2(sc1, sc1);
                const ulonglong2* wr = reinterpret_cast<const ulonglong2*>(
                    wb + ((2 * j + 1) * Cc + k) * OUTc);
                ulonglong2 wA = wr[0], wB = wr[1];
                ac[0] = ffma2(ss, wA.x, ac[0]);
                ac[1] = ffma2(ss, wA.y, ac[1]);
                ac[2] = ffma2(ss, wB.x, ac[2]);
                ac[3] = ffma2(ss, wB.y, ac[3]);
            }
        }
    }
    #pragma unroll
    for (int k = 0; k < Cc; k++) {          // c = 8
        u64 ss = pk2(s8c[k], s8c[k]);
        const ulonglong2* wr = reinterpret_cast<const ulonglong2*>(
            wb + (8 * Cc + k) * OUTc);
        ulonglong2 wA = wr[0], wB = wr[1];
        ac[0] = ffma2(ss, wA.x, ac[0]);
        ac[1] = ffma2(ss, wA.y, ac[1]);
        ac[2] = ffma2(ss, wB.x, ac[2]);
        ac[3] = ffma2(ss, wB.y, ac[3]);
    }

    // unpack, scale, relu, store two coalesced float4
    float r0f, r1f, r2f, r3f, r4f, r5f, r6f, r7f;
    upk2(ac[0], r0f, r1f);
    upk2(ac[1], r2f, r3f);
    upk2(ac[2], r4f, r5f);
    upk2(ac[3], r6f, r7f);

    float* op = out + (size_t)group * OUTc + 8 * p;
    float4 o0, o1;
    o0.x = fmaxf(r0f * invdeg, 0.0f);
    o0.y = fmaxf(r1f * invdeg, 0.0f);
    o0.z = fmaxf(r2f * invdeg, 0.0f);
    o0.w = fmaxf(r3f * invdeg, 0.0f);
    o1.x = fmaxf(r4f * invdeg, 0.0f);
    o1.y = fmaxf(r5f * invdeg, 0.0f);
    o1.z = fmaxf(r6f * invdeg, 0.0f);
    o1.w = fmaxf(r7f * invdeg, 0.0f);
    *reinterpret_cast<float4*>(op)     = o0;
    *reinterpret_cast<float4*>(op + 4) = o1;
}

extern "C" void kernel_launch(void* const* d_in, const int* in_sizes, int n_in,
                              void* d_out, int out_size)
{
    const float* x   = (const float*)d_in[0];   // (2, 20000, 9)
    const float* W   = (const float*)d_in[1];   // (9, 9, 16)
    const int*   adj = (const int*)d_in[2];     // (20000, 16)
    float*       out = (float*)d_out;           // (2, 20000, 16)

    {
        const int total   = Bc * Vc;            // 40000
        const int threads = 256;
        pad_kernel<<<(total + threads - 1) / threads, threads>>>(x);
    }
    {
        const int total   = Bc * Vc * 2;        // 80000
        const int threads = 64;
        nlayer_kernel<<<total / threads, threads>>>(W, adj, out);
    }
}